// round 13
// baseline (speedup 1.0000x reference)
#include <cuda_runtime.h>
#include <cstdint>

#define B_SZ 512
#define IN_F 512
#define OUT_F 100
#define KD 5
#define KP 6                // padded kernel dim (row stride per o)
#define OCP 600             // OUT_F * KP, padded row stride
#define OC 500              // OUT_F * KD (unpadded, T layout)
#define LOG2E 1.4426950408889634f
#define NT 32               // number of batch tiles
#define TS 16               // tile size (NT*TS = B_SZ)
#define NP 528              // NT*(NT+1)/2 unordered tile pairs
#define GRID 256            // fused grid (<= 296 resident at occ 2)

// Scratch for M = (x @ T) * log2(e), padded layout [b][o*6+k], 1.2MB
__device__ float g_M[B_SZ * OCP];
// [0] = grid-barrier arrival counter, [1] = md pair ticket.
// Reset to 0 by cudaMemsetAsync before every launch (graph-capturable).
__device__ int g_sync[2];

__device__ __forceinline__ float ex2(float x) {
    float r;
    asm("ex2.approx.f32 %0, %1;" : "=f"(r) : "f"(x));
    return r;
}

// ---------------------------------------------------------------------------
// Fused kernel: phase 1 = GEMM into g_M (+ zero out), software grid barrier,
// phase 2 = symmetric minibatch-discrimination over ticket-scheduled pairs.
// 256 blocks x 512 threads, occ 2 -> all blocks resident (barrier safe).
// ---------------------------------------------------------------------------
__global__ void __launch_bounds__(512, 2) fused_kernel(const float* __restrict__ x,
                                                       const float* __restrict__ T,
                                                       float* __restrict__ out) {
    // union: gemm uses [0..4095]=xs, [4096..8191]=red; md uses [0..9599]=ms
    __shared__ __align__(16) float pool[TS * OCP];   // 38.4KB
    __shared__ int s_p;

    const int t = threadIdx.x;
    const int bid = blockIdx.x;

    // ======================= Phase 1: GEMM =======================
    {
        float* xs = pool;              // [i][bb], 16KB
        float* red = pool + IN_F * 8;  // 4 slices, 16KB

        const int lane = t & 63;               // oc-pair lane
        const int kh = t >> 6;                 // 0..7
        const int bx = bid & 63;
        const int by = bid >> 6;               // 0..3
        const int b0 = bx * 8;
        const int oc = by * 128 + lane * 2;
        const bool ocv = (oc < OC);

        if (by == 0) {
            for (int idx = bx * 512 + t; idx < B_SZ * OUT_F; idx += 64 * 512)
                out[idx] = 0.0f;
        }

        // cooperative transpose load: x[b0+bb][i] -> xs[i*8+bb]
        for (int idx = t; idx < IN_F * 8; idx += 512) {
            int bb = idx >> 9;
            int i = idx & (IN_F - 1);
            xs[i * 8 + bb] = x[(b0 + bb) * IN_F + i];
        }
        __syncthreads();

        float accx0 = 0.f, accx1 = 0.f, accx2 = 0.f, accx3 = 0.f;
        float accx4 = 0.f, accx5 = 0.f, accx6 = 0.f, accx7 = 0.f;
        float accy0 = 0.f, accy1 = 0.f, accy2 = 0.f, accy3 = 0.f;
        float accy4 = 0.f, accy5 = 0.f, accy6 = 0.f, accy7 = 0.f;

        if (ocv) {
            const float* tp = T + (size_t)(kh * 64) * OC + oc;
            const float* xp = xs + kh * 64 * 8;
#pragma unroll 8
            for (int i = 0; i < 64; i++) {
                float2 tv = *reinterpret_cast<const float2*>(tp + i * OC);
                float4 xa = *reinterpret_cast<const float4*>(xp + i * 8);
                float4 xb = *reinterpret_cast<const float4*>(xp + i * 8 + 4);
                accx0 += xa.x * tv.x; accy0 += xa.x * tv.y;
                accx1 += xa.y * tv.x; accy1 += xa.y * tv.y;
                accx2 += xa.z * tv.x; accy2 += xa.z * tv.y;
                accx3 += xa.w * tv.x; accy3 += xa.w * tv.y;
                accx4 += xb.x * tv.x; accy4 += xb.x * tv.y;
                accx5 += xb.y * tv.x; accy5 += xb.y * tv.y;
                accx6 += xb.z * tv.x; accy6 += xb.z * tv.y;
                accx7 += xb.w * tv.x; accy7 += xb.w * tv.y;
            }
        }

#define STORE_RED(base)                                                        \
    do {                                                                       \
        float* rp = red + (base) * 1024 + lane * 2;                            \
        rp[0 * 128] = accx0; rp[0 * 128 + 1] = accy0;                          \
        rp[1 * 128] = accx1; rp[1 * 128 + 1] = accy1;                          \
        rp[2 * 128] = accx2; rp[2 * 128 + 1] = accy2;                          \
        rp[3 * 128] = accx3; rp[3 * 128 + 1] = accy3;                          \
        rp[4 * 128] = accx4; rp[4 * 128 + 1] = accy4;                          \
        rp[5 * 128] = accx5; rp[5 * 128 + 1] = accy5;                          \
        rp[6 * 128] = accx6; rp[6 * 128 + 1] = accy6;                          \
        rp[7 * 128] = accx7; rp[7 * 128 + 1] = accy7;                          \
    } while (0)
#define LOAD_RED(base)                                                         \
    do {                                                                       \
        const float* rp = red + (base) * 1024 + lane * 2;                      \
        accx0 += rp[0 * 128]; accy0 += rp[0 * 128 + 1];                        \
        accx1 += rp[1 * 128]; accy1 += rp[1 * 128 + 1];                        \
        accx2 += rp[2 * 128]; accy2 += rp[2 * 128 + 1];                        \
        accx3 += rp[3 * 128]; accy3 += rp[3 * 128 + 1];                        \
        accx4 += rp[4 * 128]; accy4 += rp[4 * 128 + 1];                        \
        accx5 += rp[5 * 128]; accy5 += rp[5 * 128 + 1];                        \
        accx6 += rp[6 * 128]; accy6 += rp[6 * 128 + 1];                        \
        accx7 += rp[7 * 128]; accy7 += rp[7 * 128 + 1];                        \
    } while (0)

        if (kh >= 4) STORE_RED(kh - 4);
        __syncthreads();
        if (kh < 4) LOAD_RED(kh);
        __syncthreads();
        if (kh == 2 || kh == 3) STORE_RED(kh - 2);
        __syncthreads();
        if (kh < 2) LOAD_RED(kh);
        __syncthreads();
        if (kh == 1) STORE_RED(0);
        __syncthreads();
        if (kh == 0) LOAD_RED(0);

        if (kh == 0 && ocv) {
            const int o0 = oc / 5, k0 = oc - o0 * 5;
            const int oc1 = oc + 1;
            const int o1 = oc1 / 5, k1 = oc1 - o1 * 5;
            const size_t off0 = (size_t)o0 * KP + k0;
            const size_t off1 = (size_t)o1 * KP + k1;
            g_M[(size_t)(b0 + 0) * OCP + off0] = accx0 * LOG2E;
            g_M[(size_t)(b0 + 0) * OCP + off1] = accy0 * LOG2E;
            g_M[(size_t)(b0 + 1) * OCP + off0] = accx1 * LOG2E;
            g_M[(size_t)(b0 + 1) * OCP + off1] = accy1 * LOG2E;
            g_M[(size_t)(b0 + 2) * OCP + off0] = accx2 * LOG2E;
            g_M[(size_t)(b0 + 2) * OCP + off1] = accy2 * LOG2E;
            g_M[(size_t)(b0 + 3) * OCP + off0] = accx3 * LOG2E;
            g_M[(size_t)(b0 + 3) * OCP + off1] = accy3 * LOG2E;
            g_M[(size_t)(b0 + 4) * OCP + off0] = accx4 * LOG2E;
            g_M[(size_t)(b0 + 4) * OCP + off1] = accy4 * LOG2E;
            g_M[(size_t)(b0 + 5) * OCP + off0] = accx5 * LOG2E;
            g_M[(size_t)(b0 + 5) * OCP + off1] = accy5 * LOG2E;
            g_M[(size_t)(b0 + 6) * OCP + off0] = accx6 * LOG2E;
            g_M[(size_t)(b0 + 6) * OCP + off1] = accy6 * LOG2E;
            g_M[(size_t)(b0 + 7) * OCP + off0] = accx7 * LOG2E;
            g_M[(size_t)(b0 + 7) * OCP + off1] = accy7 * LOG2E;
        }
#undef STORE_RED
#undef LOAD_RED
    }

    // ================== Software grid barrier ==================
    __threadfence();           // make g_M / out writes visible device-wide
    __syncthreads();
    if (t == 0) {
        atomicAdd(&g_sync[0], 1);
        while (*((volatile int*)&g_sync[0]) < GRID) __nanosleep(64);
    }
    __syncthreads();
    __threadfence();           // acquire side

    // ======================= Phase 2: MD =======================
    {
        float* ms = pool;      // 16 rows x 600 floats = 38.4KB
        const bool act = (t < 400);
        const int o = act ? (t >> 2) : 99;
        const int jl = t & 3;

        for (;;) {
            __syncthreads();   // protect ms + s_p reuse across pairs
            if (t == 0) s_p = atomicAdd(&g_sync[1], 1);
            __syncthreads();
            const int p = s_p;
            if (p >= NP) break;

            // decode p -> (ta, tb), upper triangle row-major
            int rem = p;
            int ta = 0;
            while (rem >= NT - ta) { rem -= NT - ta; ta++; }
            const int tb = ta + rem;
            const bool diag = (ta == tb);

            // stage tile_a: 2400 float4
            {
                const float4* src = reinterpret_cast<const float4*>(g_M + (size_t)ta * TS * OCP);
                float4* dst = reinterpret_cast<float4*>(ms);
                for (int i = t; i < 2400; i += 512) dst[i] = src[i];
            }

            // load 4 j-side rows into NAMED scalars
#define DECL_A(R)                                                              \
            float a##R##0, a##R##1, a##R##2, a##R##3, a##R##4;                 \
            {                                                                  \
                const int j = tb * TS + jl + 4 * (R);                          \
                const float* m = g_M + (size_t)j * OCP + o * KP;               \
                float2 v01 = *reinterpret_cast<const float2*>(m);              \
                float2 v23 = *reinterpret_cast<const float2*>(m + 2);          \
                a##R##0 = v01.x; a##R##1 = v01.y;                              \
                a##R##2 = v23.x; a##R##3 = v23.y;                              \
                a##R##4 = m[4];                                                \
            }
            DECL_A(0)
            DECL_A(1)
            DECL_A(2)
            DECL_A(3)
#undef DECL_A

            float accJ0 = 0.f, accJ1 = 0.f, accJ2 = 0.f, accJ3 = 0.f;
            __syncthreads();

            const float* mp = ms + o * KP;

#define EVAL(R, ACC)                                                           \
            {                                                                  \
                float pa = -fabsf(d01.x - a##R##0) - fabsf(d01.y - a##R##1);   \
                float qa = -fabsf(d23.x - a##R##2) - fabsf(d23.y - a##R##3);   \
                float n = (pa + qa) - fabsf(d4 - a##R##4);                     \
                float e = ex2(n);                                              \
                ACC += e;                                                      \
                loc += e;                                                      \
            }

#pragma unroll
            for (int ii = 0; ii < TS; ii++) {
                const float* m = mp + ii * OCP;
                float2 d01 = *reinterpret_cast<const float2*>(m);
                float2 d23 = *reinterpret_cast<const float2*>(m + 2);
                float d4 = m[4];
                float loc = 0.f;
                EVAL(0, accJ0)
                EVAL(1, accJ1)
                EVAL(2, accJ2)
                EVAL(3, accJ3)
                if (!diag) {
                    loc += __shfl_xor_sync(0xffffffffu, loc, 1);
                    loc += __shfl_xor_sync(0xffffffffu, loc, 2);
                    if (act && jl == 0)
                        atomicAdd(&out[(ta * TS + ii) * OUT_F + o], loc);
                }
            }
#undef EVAL

            if (act) {
                const float sub = diag ? 1.0f : 0.0f;
                atomicAdd(&out[(tb * TS + jl + 0)  * OUT_F + o], accJ0 - sub);
                atomicAdd(&out[(tb * TS + jl + 4)  * OUT_F + o], accJ1 - sub);
                atomicAdd(&out[(tb * TS + jl + 8)  * OUT_F + o], accJ2 - sub);
                atomicAdd(&out[(tb * TS + jl + 12) * OUT_F + o], accJ3 - sub);
            }
        }
    }
}

extern "C" void kernel_launch(void* const* d_in, const int* in_sizes, int n_in,
                              void* d_out, int out_size) {
    const float* x = (const float*)d_in[0];   // [512, 512]
    const float* T = (const float*)d_in[1];   // [512, 100, 5] -> [512, 500]
    float* out = (float*)d_out;               // [512, 100]

    // reset barrier + ticket counters (graph-capturable async memset)
    void* sp = nullptr;
    cudaGetSymbolAddress(&sp, g_sync);
    cudaMemsetAsync(sp, 0, 2 * sizeof(int));

    fused_kernel<<<GRID, 512>>>(x, T, out);
}